// round 1
// baseline (speedup 1.0000x reference)
#include <cuda_runtime.h>
#include <stdint.h>

// Problem constants (fixed by the reference)
#define NRELS 64
#define EPR   16384                 // edges per relation (uniform sections)
#define NE    (NRELS * EPR)         // 1,048,576 edges
#define NN    100000                // nodes
#define F     128                   // in_feat == out_feat
#define NB    16                    // bases
#define AS    132                   // padded A-tile row stride (floats), 16B-aligned

#define SMEM_BYTES ((F * F + F * AS) * 4)   // 133120 bytes

// Scratch: per-relation composed weights [64,128,128] = 4 MB
__device__ float g_W[NRELS * F * F];
// 1 => indices are int64, 0 => int32 (jax x64-flag ambiguity)
__device__ int g_idx64;

// ---------------------------------------------------------------------------
// Detect whether src/dst are int64 or int32 (values < 100000, so if the data
// is really int64, every high 32-bit word is zero; if int32, the "high words"
// are random node ids, nonzero w.p. ~1-1e-5 each).
// ---------------------------------------------------------------------------
__global__ void detect_kernel(const void* __restrict__ src) {
    if (threadIdx.x == 0 && blockIdx.x == 0) {
        const unsigned long long* p = (const unsigned long long*)src;
        int all0 = 1;
#pragma unroll
        for (int i = 0; i < 8; i++) all0 &= ((p[i] >> 32) == 0ull);
        g_idx64 = all0;
    }
}

__device__ __forceinline__ int load_idx(const void* p, int i, int is64) {
    return is64 ? (int)((const long long*)p)[i] : ((const int*)p)[i];
}

// ---------------------------------------------------------------------------
// Basis composition: g_W[r] = sum_b w_comp[r][b] * weight[b]
// 512 blocks: 8 chunks of 2048 elements per relation.
// ---------------------------------------------------------------------------
__global__ void basis_kernel(const float* __restrict__ weight,
                             const float* __restrict__ wcomp) {
    int r = blockIdx.x >> 3;
    int c = blockIdx.x & 7;
    __shared__ float s_wc[NB];
    if (threadIdx.x < NB) s_wc[threadIdx.x] = wcomp[r * NB + threadIdx.x];
    __syncthreads();
    int base = c * 2048;
    for (int p = threadIdx.x; p < 2048; p += blockDim.x) {
        float acc = 0.f;
#pragma unroll
        for (int b = 0; b < NB; b++)
            acc = fmaf(s_wc[b], weight[b * F * F + base + p], acc);
        g_W[r * F * F + base + p] = acc;
    }
}

// ---------------------------------------------------------------------------
// Self-loop + bias: out[n] = h_bias + feat[n] @ loop_weight  (no relu yet)
// 128-node x 128-out tile, K=128, 8x8 register microtile per thread.
// ---------------------------------------------------------------------------
__global__ void selfloop_kernel(const float* __restrict__ feat,
                                const float* __restrict__ lw,
                                const float* __restrict__ bias,
                                float* __restrict__ out) {
    extern __shared__ float sm[];
    float* Ws = sm;            // [128][128]
    float* A  = sm + F * F;    // [128][AS] transposed: A[k][node]
    int tid = threadIdx.x;
    int n0 = blockIdx.x * 128;

    // Stage loop_weight [in=k][out] (natural row-major layout)
    {
        const float4* wg = (const float4*)lw;
        float4* ws4 = (float4*)Ws;
#pragma unroll
        for (int i = 0; i < 16; i++) ws4[tid + 256 * i] = wg[tid + 256 * i];
    }
    // Gather + transpose feat rows: 2 threads per node, 64 k each
    {
        int e  = tid >> 1;
        int kh = (tid & 1) << 6;
        int n  = n0 + e;
        int nn = (n < NN) ? n : 0;
        const float4* row = (const float4*)(feat + (size_t)nn * F + kh);
#pragma unroll
        for (int q = 0; q < 16; q++) {
            float4 v = row[q];
            int k = kh + q * 4;
            A[(k + 0) * AS + e] = v.x;
            A[(k + 1) * AS + e] = v.y;
            A[(k + 2) * AS + e] = v.z;
            A[(k + 3) * AS + e] = v.w;
        }
    }
    __syncthreads();

    int tx = tid & 15, ty = tid >> 4;
    float acc[8][8];
#pragma unroll
    for (int i = 0; i < 8; i++)
#pragma unroll
        for (int j = 0; j < 8; j++) acc[i][j] = 0.f;

    const float* Ap = A + ty * 8;
    const float* Bp = Ws + tx * 4;
#pragma unroll 8
    for (int k = 0; k < F; k++) {
        float4 a0 = *(const float4*)(Ap + k * AS);
        float4 a1 = *(const float4*)(Ap + k * AS + 4);
        float4 b0 = *(const float4*)(Bp + k * F);
        float4 b1 = *(const float4*)(Bp + k * F + 64);
        float av[8] = {a0.x, a0.y, a0.z, a0.w, a1.x, a1.y, a1.z, a1.w};
        float bv[8] = {b0.x, b0.y, b0.z, b0.w, b1.x, b1.y, b1.z, b1.w};
#pragma unroll
        for (int i = 0; i < 8; i++)
#pragma unroll
            for (int j = 0; j < 8; j++)
                acc[i][j] = fmaf(av[i], bv[j], acc[i][j]);
    }

    float4 bb0 = *(const float4*)(bias + tx * 4);
    float4 bb1 = *(const float4*)(bias + 64 + tx * 4);
#pragma unroll
    for (int i = 0; i < 8; i++) {
        int n = n0 + ty * 8 + i;
        if (n < NN) {
            float* po = out + (size_t)n * F + tx * 4;
            *(float4*)po =
                make_float4(acc[i][0] + bb0.x, acc[i][1] + bb0.y,
                            acc[i][2] + bb0.z, acc[i][3] + bb0.w);
            *(float4*)(po + 64) =
                make_float4(acc[i][4] + bb1.x, acc[i][5] + bb1.y,
                            acc[i][6] + bb1.z, acc[i][7] + bb1.w);
        }
    }
}

// ---------------------------------------------------------------------------
// Edge messages: per block 128 edges (all one relation), C = gather(A) @ W_rel,
// scale by norm, v4 reduce-add into out[dst].
// ---------------------------------------------------------------------------
__global__ void edge_kernel(const float* __restrict__ feat,
                            const float* __restrict__ norm,
                            const void* __restrict__ srcv,
                            const void* __restrict__ dstv,
                            float* __restrict__ out) {
    extern __shared__ float sm[];
    float* Ws = sm;
    float* A  = sm + F * F;
    int tid = threadIdx.x;
    int e0  = blockIdx.x * 128;
    int rel = e0 >> 14;          // / 16384
    int is64 = g_idx64;

    // Stage W_rel
    {
        const float4* wg = (const float4*)(g_W + rel * F * F);
        float4* ws4 = (float4*)Ws;
#pragma unroll
        for (int i = 0; i < 16; i++) ws4[tid + 256 * i] = wg[tid + 256 * i];
    }
    // Gather + transpose source rows
    {
        int e  = tid >> 1;
        int kh = (tid & 1) << 6;
        int s  = load_idx(srcv, e0 + e, is64);
        const float4* row = (const float4*)(feat + (size_t)s * F + kh);
#pragma unroll
        for (int q = 0; q < 16; q++) {
            float4 v = row[q];
            int k = kh + q * 4;
            A[(k + 0) * AS + e] = v.x;
            A[(k + 1) * AS + e] = v.y;
            A[(k + 2) * AS + e] = v.z;
            A[(k + 3) * AS + e] = v.w;
        }
    }
    __syncthreads();

    int tx = tid & 15, ty = tid >> 4;
    float acc[8][8];
#pragma unroll
    for (int i = 0; i < 8; i++)
#pragma unroll
        for (int j = 0; j < 8; j++) acc[i][j] = 0.f;

    const float* Ap = A + ty * 8;
    const float* Bp = Ws + tx * 4;
#pragma unroll 8
    for (int k = 0; k < F; k++) {
        float4 a0 = *(const float4*)(Ap + k * AS);
        float4 a1 = *(const float4*)(Ap + k * AS + 4);
        float4 b0 = *(const float4*)(Bp + k * F);
        float4 b1 = *(const float4*)(Bp + k * F + 64);
        float av[8] = {a0.x, a0.y, a0.z, a0.w, a1.x, a1.y, a1.z, a1.w};
        float bv[8] = {b0.x, b0.y, b0.z, b0.w, b1.x, b1.y, b1.z, b1.w};
#pragma unroll
        for (int i = 0; i < 8; i++)
#pragma unroll
            for (int j = 0; j < 8; j++)
                acc[i][j] = fmaf(av[i], bv[j], acc[i][j]);
    }

#pragma unroll
    for (int i = 0; i < 8; i++) {
        int e = e0 + ty * 8 + i;
        float nm = norm[e];
        int d = load_idx(dstv, e, is64);
        float* po = out + (size_t)d * F + tx * 4;
        float x0 = acc[i][0] * nm, x1 = acc[i][1] * nm;
        float x2 = acc[i][2] * nm, x3 = acc[i][3] * nm;
        float y0 = acc[i][4] * nm, y1 = acc[i][5] * nm;
        float y2 = acc[i][6] * nm, y3 = acc[i][7] * nm;
        asm volatile("red.global.add.v4.f32 [%0], {%1,%2,%3,%4};"
                     :: "l"(po), "f"(x0), "f"(x1), "f"(x2), "f"(x3) : "memory");
        asm volatile("red.global.add.v4.f32 [%0], {%1,%2,%3,%4};"
                     :: "l"(po + 64), "f"(y0), "f"(y1), "f"(y2), "f"(y3) : "memory");
    }
}

// ---------------------------------------------------------------------------
// Final ReLU over out
// ---------------------------------------------------------------------------
__global__ void relu_kernel(float* __restrict__ out) {
    int n4 = NN * F / 4;
    float4* p = (float4*)out;
    for (int i = blockIdx.x * blockDim.x + threadIdx.x; i < n4;
         i += gridDim.x * blockDim.x) {
        float4 v = p[i];
        v.x = fmaxf(v.x, 0.f);
        v.y = fmaxf(v.y, 0.f);
        v.z = fmaxf(v.z, 0.f);
        v.w = fmaxf(v.w, 0.f);
        p[i] = v;
    }
}

extern "C" void kernel_launch(void* const* d_in, const int* in_sizes, int n_in,
                              void* d_out, int out_size) {
    const float* feat   = (const float*)d_in[0];
    const float* weight = (const float*)d_in[1];
    const float* wcomp  = (const float*)d_in[2];
    const float* bias   = (const float*)d_in[3];
    const float* lw     = (const float*)d_in[4];
    const float* norm   = (const float*)d_in[5];
    const void*  src    = d_in[6];
    const void*  dst    = d_in[7];
    float* out = (float*)d_out;

    cudaFuncSetAttribute(edge_kernel,
                         cudaFuncAttributeMaxDynamicSharedMemorySize, SMEM_BYTES);
    cudaFuncSetAttribute(selfloop_kernel,
                         cudaFuncAttributeMaxDynamicSharedMemorySize, SMEM_BYTES);

    detect_kernel<<<1, 32>>>(src);
    basis_kernel<<<NRELS * 8, 256>>>(weight, wcomp);
    selfloop_kernel<<<(NN + 127) / 128, 256, SMEM_BYTES>>>(feat, lw, bias, out);
    edge_kernel<<<NE / 128, 256, SMEM_BYTES>>>(feat, norm, src, dst, out);
    relu_kernel<<<2048, 256>>>(out);
}

// round 2
// speedup vs baseline: 1.1287x; 1.1287x over previous
#include <cuda_runtime.h>
#include <stdint.h>

// Problem constants (fixed by the reference)
#define NRELS 64
#define EPR   16384                 // edges per relation (uniform sections)
#define NE    (NRELS * EPR)         // 1,048,576 edges
#define NN    100000                // nodes
#define F     128                   // in_feat == out_feat
#define NB    16                    // bases
#define ET    256                   // edge-tile per block
#define ES    260                   // padded A-tile row stride (floats)

#define SMEM_BYTES ((F * F + F * ES) * 4)   // 196608 + ... = 198656? -> (16384+33280)*4 = 198656

// Scratch: per-relation composed weights [64,128,128] = 4 MB
__device__ float g_W[NRELS * F * F];
// 1 => indices are int64, 0 => int32 (jax x64-flag ambiguity)
__device__ int g_idx64;

// ---------------------------------------------------------------------------
// Detect whether src/dst are int64 or int32.
// ---------------------------------------------------------------------------
__global__ void detect_kernel(const void* __restrict__ src) {
    if (threadIdx.x == 0 && blockIdx.x == 0) {
        const unsigned long long* p = (const unsigned long long*)src;
        int all0 = 1;
#pragma unroll
        for (int i = 0; i < 8; i++) all0 &= ((p[i] >> 32) == 0ull);
        g_idx64 = all0;
    }
}

__device__ __forceinline__ int load_idx(const void* p, int i, int is64) {
    return is64 ? (int)((const long long*)p)[i] : ((const int*)p)[i];
}

// ---------------------------------------------------------------------------
// Basis composition: g_W[r] = sum_b w_comp[r][b] * weight[b]
// ---------------------------------------------------------------------------
__global__ void basis_kernel(const float* __restrict__ weight,
                             const float* __restrict__ wcomp) {
    int r = blockIdx.x >> 3;
    int c = blockIdx.x & 7;
    __shared__ float s_wc[NB];
    if (threadIdx.x < NB) s_wc[threadIdx.x] = wcomp[r * NB + threadIdx.x];
    __syncthreads();
    int base = c * 2048;
    for (int p = threadIdx.x; p < 2048; p += blockDim.x) {
        float acc = 0.f;
#pragma unroll
        for (int b = 0; b < NB; b++)
            acc = fmaf(s_wc[b], weight[b * F * F + base + p], acc);
        g_W[r * F * F + base + p] = acc;
    }
}

// ---------------------------------------------------------------------------
// Shared GEMM core: C[256 rows x 128 out] = A_sm(k-major)[128][ES] x W_sm[128][128]
// 512 threads, 8x8 register microtile.
// ---------------------------------------------------------------------------
__device__ __forceinline__ void tile_gemm(const float* __restrict__ A,
                                          const float* __restrict__ Ws,
                                          float acc[8][8], int tx, int ty) {
    const float* Ap = A + ty * 8;
    const float* Bp = Ws + tx * 4;
#pragma unroll 8
    for (int k = 0; k < F; k++) {
        float4 a0 = *(const float4*)(Ap + k * ES);
        float4 a1 = *(const float4*)(Ap + k * ES + 4);
        float4 b0 = *(const float4*)(Bp + k * F);
        float4 b1 = *(const float4*)(Bp + k * F + 64);
        float av[8] = {a0.x, a0.y, a0.z, a0.w, a1.x, a1.y, a1.z, a1.w};
        float bv[8] = {b0.x, b0.y, b0.z, b0.w, b1.x, b1.y, b1.z, b1.w};
#pragma unroll
        for (int i = 0; i < 8; i++)
#pragma unroll
            for (int j = 0; j < 8; j++)
                acc[i][j] = fmaf(av[i], bv[j], acc[i][j]);
    }
}

// ---------------------------------------------------------------------------
// Self-loop + bias: out[n] = h_bias + feat[n] @ loop_weight  (no relu yet)
// ---------------------------------------------------------------------------
__global__ void __launch_bounds__(512, 1)
selfloop_kernel(const float* __restrict__ feat,
                const float* __restrict__ lw,
                const float* __restrict__ bias,
                float* __restrict__ out) {
    extern __shared__ float sm[];
    float* Ws = sm;            // [128][128]
    float* A  = sm + F * F;    // [128][ES] transposed: A[k][node]
    int tid = threadIdx.x;
    int n0 = blockIdx.x * ET;

    // Stage loop_weight [in=k][out]
    {
        const float4* wg = (const float4*)lw;
        float4* ws4 = (float4*)Ws;
#pragma unroll
        for (int i = 0; i < 8; i++) ws4[tid + 512 * i] = wg[tid + 512 * i];
    }
    // Gather + transpose feat rows: 2 threads per node, 64 k each
    {
        int e  = tid >> 1;
        int kh = (tid & 1) << 6;
        int n  = n0 + e;
        int nn = (n < NN) ? n : 0;
        const float4* row = (const float4*)(feat + (size_t)nn * F + kh);
#pragma unroll
        for (int q = 0; q < 16; q++) {
            float4 v = row[q];
            int k = kh + q * 4;
            A[(k + 0) * ES + e] = v.x;
            A[(k + 1) * ES + e] = v.y;
            A[(k + 2) * ES + e] = v.z;
            A[(k + 3) * ES + e] = v.w;
        }
    }
    __syncthreads();

    int tx = tid & 15, ty = tid >> 4;
    float acc[8][8];
#pragma unroll
    for (int i = 0; i < 8; i++)
#pragma unroll
        for (int j = 0; j < 8; j++) acc[i][j] = 0.f;

    tile_gemm(A, Ws, acc, tx, ty);

    float4 bb0 = *(const float4*)(bias + tx * 4);
    float4 bb1 = *(const float4*)(bias + 64 + tx * 4);
#pragma unroll
    for (int i = 0; i < 8; i++) {
        int n = n0 + ty * 8 + i;
        if (n < NN) {
            float* po = out + (size_t)n * F + tx * 4;
            *(float4*)po =
                make_float4(acc[i][0] + bb0.x, acc[i][1] + bb0.y,
                            acc[i][2] + bb0.z, acc[i][3] + bb0.w);
            *(float4*)(po + 64) =
                make_float4(acc[i][4] + bb1.x, acc[i][5] + bb1.y,
                            acc[i][6] + bb1.z, acc[i][7] + bb1.w);
        }
    }
}

// ---------------------------------------------------------------------------
// Edge messages: per block 256 edges (one relation), C = gather(A) @ W_rel,
// scale by norm, v4 reduce-add into out[dst].
// ---------------------------------------------------------------------------
__global__ void __launch_bounds__(512, 1)
edge_kernel(const float* __restrict__ feat,
            const float* __restrict__ norm,
            const void* __restrict__ srcv,
            const void* __restrict__ dstv,
            float* __restrict__ out) {
    extern __shared__ float sm[];
    float* Ws = sm;
    float* A  = sm + F * F;
    int tid = threadIdx.x;
    int e0  = blockIdx.x * ET;
    int rel = e0 >> 14;          // / 16384
    int is64 = g_idx64;

    // Stage W_rel
    {
        const float4* wg = (const float4*)(g_W + rel * F * F);
        float4* ws4 = (float4*)Ws;
#pragma unroll
        for (int i = 0; i < 8; i++) ws4[tid + 512 * i] = wg[tid + 512 * i];
    }
    // Gather + transpose source rows
    {
        int e  = tid >> 1;
        int kh = (tid & 1) << 6;
        int s  = load_idx(srcv, e0 + e, is64);
        const float4* row = (const float4*)(feat + (size_t)s * F + kh);
#pragma unroll
        for (int q = 0; q < 16; q++) {
            float4 v = row[q];
            int k = kh + q * 4;
            A[(k + 0) * ES + e] = v.x;
            A[(k + 1) * ES + e] = v.y;
            A[(k + 2) * ES + e] = v.z;
            A[(k + 3) * ES + e] = v.w;
        }
    }
    __syncthreads();

    int tx = tid & 15, ty = tid >> 4;
    float acc[8][8];
#pragma unroll
    for (int i = 0; i < 8; i++)
#pragma unroll
        for (int j = 0; j < 8; j++) acc[i][j] = 0.f;

    tile_gemm(A, Ws, acc, tx, ty);

#pragma unroll
    for (int i = 0; i < 8; i++) {
        int e = e0 + ty * 8 + i;
        float nm = norm[e];
        int d = load_idx(dstv, e, is64);
        float* po = out + (size_t)d * F + tx * 4;
        float x0 = acc[i][0] * nm, x1 = acc[i][1] * nm;
        float x2 = acc[i][2] * nm, x3 = acc[i][3] * nm;
        float y0 = acc[i][4] * nm, y1 = acc[i][5] * nm;
        float y2 = acc[i][6] * nm, y3 = acc[i][7] * nm;
        asm volatile("red.global.add.v4.f32 [%0], {%1,%2,%3,%4};"
                     :: "l"(po), "f"(x0), "f"(x1), "f"(x2), "f"(x3) : "memory");
        asm volatile("red.global.add.v4.f32 [%0], {%1,%2,%3,%4};"
                     :: "l"(po + 64), "f"(y0), "f"(y1), "f"(y2), "f"(y3) : "memory");
    }
}

// ---------------------------------------------------------------------------
// Final ReLU over out
// ---------------------------------------------------------------------------
__global__ void relu_kernel(float* __restrict__ out) {
    int n4 = NN * F / 4;
    float4* p = (float4*)out;
    for (int i = blockIdx.x * blockDim.x + threadIdx.x; i < n4;
         i += gridDim.x * blockDim.x) {
        float4 v = p[i];
        v.x = fmaxf(v.x, 0.f);
        v.y = fmaxf(v.y, 0.f);
        v.z = fmaxf(v.z, 0.f);
        v.w = fmaxf(v.w, 0.f);
        p[i] = v;
    }
}

extern "C" void kernel_launch(void* const* d_in, const int* in_sizes, int n_in,
                              void* d_out, int out_size) {
    const float* feat   = (const float*)d_in[0];
    const float* weight = (const float*)d_in[1];
    const float* wcomp  = (const float*)d_in[2];
    const float* bias   = (const float*)d_in[3];
    const float* lw     = (const float*)d_in[4];
    const float* norm   = (const float*)d_in[5];
    const void*  src    = d_in[6];
    const void*  dst    = d_in[7];
    float* out = (float*)d_out;

    cudaFuncSetAttribute(edge_kernel,
                         cudaFuncAttributeMaxDynamicSharedMemorySize, SMEM_BYTES);
    cudaFuncSetAttribute(selfloop_kernel,
                         cudaFuncAttributeMaxDynamicSharedMemorySize, SMEM_BYTES);

    detect_kernel<<<1, 32>>>(src);
    basis_kernel<<<NRELS * 8, 256>>>(weight, wcomp);
    selfloop_kernel<<<(NN + ET - 1) / ET, 512, SMEM_BYTES>>>(feat, lw, bias, out);
    edge_kernel<<<NE / ET, 512, SMEM_BYTES>>>(feat, norm, src, dst, out);
    relu_kernel<<<2048, 256>>>(out);
}

// round 7
// speedup vs baseline: 1.1907x; 1.0550x over previous
#include <cuda_runtime.h>
#include <cuda_bf16.h>
#include <stdint.h>

// Problem constants (fixed by the reference)
#define NRELS 64
#define EPR   16384
#define NE    (NRELS * EPR)         // 1,048,576 edges
#define NN    100000
#define F     128                   // in_feat == out_feat
#define NB    16

// ---------------- fp32 selfloop tile params (unchanged) ---------------------
#define ET    256
#define ES    260
#define SL_SMEM ((F * F + F * ES) * 4)

// ---------------- mma.sync edge kernel params -------------------------------
#define EM    128                   // edges per block
#define TILE_BYTES 32768            // 128 rows x 128 bf16 (256 B/row, XOR swizzle)
#define OFF_AHI 0
#define OFF_ALO 32768
#define OFF_WHI 65536
#define OFF_WLO 98304
#define EDGE_SMEM 131072
#define CSTRIDE 132                 // epilogue C row stride (floats), 16B-aligned rows

// Per-relation W^T hi/lo bf16, pre-laid-out as the exact 32KB smem tile image
__device__ __align__(16) unsigned char g_Whi[NRELS * TILE_BYTES]; // 2 MB
__device__ __align__(16) unsigned char g_Wlo[NRELS * TILE_BYTES]; // 2 MB
__device__ int g_idx64;

// ---------------------------------------------------------------------------
// Helpers
// ---------------------------------------------------------------------------
__device__ __forceinline__ uint32_t smem_u32(const void* p) {
    uint32_t a;
    asm("{ .reg .u64 t; cvta.to.shared.u64 t, %1; cvt.u32.u64 %0, t; }"
        : "=r"(a) : "l"(p));
    return a;
}

__device__ __forceinline__ uint32_t bf2_as_u32(__nv_bfloat162 v) {
    union { __nv_bfloat162 b; uint32_t u; } c;
    c.b = v;
    return c.u;
}

#define LDSM4(r0, r1, r2, r3, addr) \
    asm volatile("ldmatrix.sync.aligned.m8n8.x4.shared.b16 {%0,%1,%2,%3}, [%4];" \
                 : "=r"(r0), "=r"(r1), "=r"(r2), "=r"(r3) : "r"(addr))

#define MMA_BF16(d, a0, a1, a2, a3, b0, b1) \
    asm volatile("mma.sync.aligned.m16n8k16.row.col.f32.bf16.bf16.f32 " \
                 "{%0,%1,%2,%3}, {%4,%5,%6,%7}, {%8,%9}, {%0,%1,%2,%3};" \
                 : "+f"((d)[0]), "+f"((d)[1]), "+f"((d)[2]), "+f"((d)[3]) \
                 : "r"(a0), "r"(a1), "r"(a2), "r"(a3), "r"(b0), "r"(b1))

// bf16 tile address: row stride 256 B, 16B-chunk XOR swizzle (c ^= row&7)
__device__ __forceinline__ uint32_t btile_addr(int row, int col) {
    return (uint32_t)(row * 256 + ((((col >> 3) ^ (row & 7)) & 15) << 4)
                      + ((col & 7) << 1));
}

// ---------------------------------------------------------------------------
__global__ void detect_kernel(const void* __restrict__ src) {
    if (threadIdx.x == 0 && blockIdx.x == 0) {
        const unsigned long long* p = (const unsigned long long*)src;
        int all0 = 1;
#pragma unroll
        for (int i = 0; i < 8; i++) all0 &= ((p[i] >> 32) == 0ull);
        g_idx64 = all0;
    }
}
__device__ __forceinline__ int load_idx(const void* p, int i, int is64) {
    return is64 ? (int)((const long long*)p)[i] : ((const int*)p)[i];
}

// ---------------------------------------------------------------------------
// Basis composition -> per-relation W^T hi/lo bf16 tile images.
// Tile row = out index o (N), tile col = k. W^T[o][k] = Wc[k][o].
// hi = truncate-to-bf16(fp32 top 16 bits), lo = round(v - hi).
// ---------------------------------------------------------------------------
__global__ void basis_kernel(const float* __restrict__ weight,
                             const float* __restrict__ wcomp) {
    int r = blockIdx.x;
    __shared__ float s_wc[NB];
    if (threadIdx.x < NB) s_wc[threadIdx.x] = wcomp[r * NB + threadIdx.x];
    __syncthreads();
    for (int idx = threadIdx.x; idx < F * F; idx += blockDim.x) {
        int o = idx >> 7;
        int k = idx & 127;
        float acc = 0.f;
#pragma unroll
        for (int b = 0; b < NB; b++)
            acc = fmaf(s_wc[b], weight[b * F * F + k * F + o], acc);
        uint32_t u = __float_as_uint(acc);
        float hf = __uint_as_float(u & 0xffff0000u);
        __nv_bfloat16 lo = __float2bfloat16(acc - hf);
        uint32_t a = btile_addr(o, k);
        *(unsigned short*)(g_Whi + r * TILE_BYTES + a) = (unsigned short)(u >> 16);
        *(unsigned short*)(g_Wlo + r * TILE_BYTES + a) = __bfloat16_as_ushort(lo);
    }
}

// ---------------------------------------------------------------------------
// Self-loop + bias (fp32)
// ---------------------------------------------------------------------------
__global__ void __launch_bounds__(512, 1)
selfloop_kernel(const float* __restrict__ feat,
                const float* __restrict__ lw,
                const float* __restrict__ bias,
                float* __restrict__ out) {
    extern __shared__ float sm[];
    float* Ws = sm;
    float* A  = sm + F * F;
    int tid = threadIdx.x;
    int n0 = blockIdx.x * ET;
    {
        const float4* wg = (const float4*)lw;
        float4* ws4 = (float4*)Ws;
#pragma unroll
        for (int i = 0; i < 8; i++) ws4[tid + 512 * i] = wg[tid + 512 * i];
    }
    {
        int e  = tid >> 1;
        int kh = (tid & 1) << 6;
        int n  = n0 + e;
        int nn = (n < NN) ? n : 0;
        const float4* row = (const float4*)(feat + (size_t)nn * F + kh);
#pragma unroll
        for (int q = 0; q < 16; q++) {
            float4 v = row[q];
            int k = kh + q * 4;
            A[(k + 0) * ES + e] = v.x;
            A[(k + 1) * ES + e] = v.y;
            A[(k + 2) * ES + e] = v.z;
            A[(k + 3) * ES + e] = v.w;
        }
    }
    __syncthreads();

    int tx = tid & 15, ty = tid >> 4;
    float acc[8][8];
#pragma unroll
    for (int i = 0; i < 8; i++)
#pragma unroll
        for (int j = 0; j < 8; j++) acc[i][j] = 0.f;

    const float* Ap = A + ty * 8;
    const float* Bp = Ws + tx * 4;
#pragma unroll 8
    for (int k = 0; k < F; k++) {
        float4 a0 = *(const float4*)(Ap + k * ES);
        float4 a1 = *(const float4*)(Ap + k * ES + 4);
        float4 b0 = *(const float4*)(Bp + k * F);
        float4 b1 = *(const float4*)(Bp + k * F + 64);
        float av[8] = {a0.x, a0.y, a0.z, a0.w, a1.x, a1.y, a1.z, a1.w};
        float bv[8] = {b0.x, b0.y, b0.z, b0.w, b1.x, b1.y, b1.z, b1.w};
#pragma unroll
        for (int i = 0; i < 8; i++)
#pragma unroll
            for (int j = 0; j < 8; j++)
                acc[i][j] = fmaf(av[i], bv[j], acc[i][j]);
    }
    float4 bb0 = *(const float4*)(bias + tx * 4);
    float4 bb1 = *(const float4*)(bias + 64 + tx * 4);
#pragma unroll
    for (int i = 0; i < 8; i++) {
        int n = n0 + ty * 8 + i;
        if (n < NN) {
            float* po = out + (size_t)n * F + tx * 4;
            *(float4*)po = make_float4(acc[i][0] + bb0.x, acc[i][1] + bb0.y,
                                       acc[i][2] + bb0.z, acc[i][3] + bb0.w);
            *(float4*)(po + 64) = make_float4(acc[i][4] + bb1.x, acc[i][5] + bb1.y,
                                              acc[i][6] + bb1.z, acc[i][7] + bb1.w);
        }
    }
}

// ---------------------------------------------------------------------------
// Edge messages via mma.sync bf16 split: per block 128 edges (one relation).
// D = A_hi@Whi^T + A_hi@Wlo^T + A_lo@Whi^T  (fp32 accum in registers)
// then scale by norm and red.global.add.v4 into out[dst].
// ---------------------------------------------------------------------------
__global__ void __launch_bounds__(256, 1)
edge_kernel(const float* __restrict__ feat,
            const float* __restrict__ norm,
            const void* __restrict__ srcv,
            const void* __restrict__ dstv,
            float* __restrict__ out) {
    extern __shared__ char smem[];
    uint32_t sb = smem_u32(smem);
    int tid = threadIdx.x;
    int l   = tid & 31;
    int wid = tid >> 5;
    int wm  = wid & 3;               // m-block: rows wm*32 .. +31
    int wn  = wid >> 2;              // n-block: cols wn*64 .. +63
    int e0  = blockIdx.x * EM;
    int rel = e0 >> 14;
    int is64 = g_idx64;

    // Stage W hi/lo (pre-swizzled 32KB images, straight float4 copy)
    {
        const float4* wh = (const float4*)(g_Whi + rel * TILE_BYTES);
        const float4* wl = (const float4*)(g_Wlo + rel * TILE_BYTES);
        float4* sh = (float4*)(smem + OFF_WHI);
        float4* sl = (float4*)(smem + OFF_WLO);
#pragma unroll
        for (int i = 0; i < 8; i++) {
            sh[tid + 256 * i] = wh[tid + 256 * i];
            sl[tid + 256 * i] = wl[tid + 256 * i];
        }
    }
    // Gather source rows, split fp32 -> bf16 hi(trunc)/lo, store swizzled
    {
        int e  = tid >> 1;               // 0..127
        int kh = (tid & 1) << 6;         // 0 or 64
        int s  = load_idx(srcv, e0 + e, is64);
        const float4* row = (const float4*)(feat + (size_t)s * F + kh);
        uint32_t rbase = (uint32_t)(e * 256);
        uint32_t rswz  = (uint32_t)(e & 7);
#pragma unroll
        for (int q = 0; q < 8; q++) {
            float4 v0 = row[2 * q];
            float4 v1 = row[2 * q + 1];
            uint32_t u0 = __float_as_uint(v0.x), u1 = __float_as_uint(v0.y);
            uint32_t u2 = __float_as_uint(v0.z), u3 = __float_as_uint(v0.w);
            uint32_t u4 = __float_as_uint(v1.x), u5 = __float_as_uint(v1.y);
            uint32_t u6 = __float_as_uint(v1.z), u7 = __float_as_uint(v1.w);
            uint4 hv;
            hv.x = __byte_perm(u0, u1, 0x7632);
            hv.y = __byte_perm(u2, u3, 0x7632);
            hv.z = __byte_perm(u4, u5, 0x7632);
            hv.w = __byte_perm(u6, u7, 0x7632);
            float l0 = v0.x - __uint_as_float(u0 & 0xffff0000u);
            float l1 = v0.y - __uint_as_float(u1 & 0xffff0000u);
            float l2 = v0.z - __uint_as_float(u2 & 0xffff0000u);
            float l3 = v0.w - __uint_as_float(u3 & 0xffff0000u);
            float l4 = v1.x - __uint_as_float(u4 & 0xffff0000u);
            float l5 = v1.y - __uint_as_float(u5 & 0xffff0000u);
            float l6 = v1.z - __uint_as_float(u6 & 0xffff0000u);
            float l7 = v1.w - __uint_as_float(u7 & 0xffff0000u);
            uint4 lv;
            lv.x = bf2_as_u32(__floats2bfloat162_rn(l0, l1));
            lv.y = bf2_as_u32(__floats2bfloat162_rn(l2, l3));
            lv.z = bf2_as_u32(__floats2bfloat162_rn(l4, l5));
            lv.w = bf2_as_u32(__floats2bfloat162_rn(l6, l7));
            uint32_t chunk = (uint32_t)((kh >> 3) + q);
            uint32_t off = rbase + ((chunk ^ rswz) << 4);
            *(uint4*)(smem + OFF_AHI + off) = hv;
            *(uint4*)(smem + OFF_ALO + off) = lv;
        }
    }
    __syncthreads();

    // Fragment address precompute
    uint32_t aOff[2], aSwz[2];
#pragma unroll
    for (int mi = 0; mi < 2; mi++) {
        int r = wm * 32 + mi * 16 + (l & 15);
        aOff[mi] = (uint32_t)(r * 256);
        aSwz[mi] = (uint32_t)(r & 7);
    }
    uint32_t aSel = (uint32_t)(l >> 4);
    uint32_t bOff[4], bSwz[4];
#pragma unroll
    for (int g = 0; g < 4; g++) {
        int r = wn * 64 + (2 * g + (l >> 4)) * 8 + (l & 7);
        bOff[g] = (uint32_t)(r * 256);
        bSwz[g] = (uint32_t)(r & 7);
    }
    uint32_t bSel = (uint32_t)((l >> 3) & 1);

    float acc[2][8][4];
#pragma unroll
    for (int mi = 0; mi < 2; mi++)
#pragma unroll
        for (int nb = 0; nb < 8; nb++)
#pragma unroll
            for (int j = 0; j < 4; j++) acc[mi][nb][j] = 0.f;

#pragma unroll
    for (int ks = 0; ks < 8; ks++) {
        uint32_t cA = 2 * ks + aSel;
        uint32_t cB = 2 * ks + bSel;
        uint32_t ah[2][4], al[2][4];
#pragma unroll
        for (int mi = 0; mi < 2; mi++) {
            uint32_t ad = sb + aOff[mi] + (((cA ^ aSwz[mi]) & 15) << 4);
            LDSM4(ah[mi][0], ah[mi][1], ah[mi][2], ah[mi][3], ad + OFF_AHI);
            LDSM4(al[mi][0], al[mi][1], al[mi][2], al[mi][3], ad + OFF_ALO);
        }
        uint32_t bh[8][2], bl[8][2];
#pragma unroll
        for (int g = 0; g < 4; g++) {
            uint32_t bd = sb + bOff[g] + (((cB ^ bSwz[g]) & 15) << 4);
            LDSM4(bh[2 * g][0], bh[2 * g][1], bh[2 * g + 1][0], bh[2 * g + 1][1],
                  bd + OFF_WHI);
            LDSM4(bl[2 * g][0], bl[2 * g][1], bl[2 * g + 1][0], bl[2 * g + 1][1],
                  bd + OFF_WLO);
        }
#pragma unroll
        for (int mi = 0; mi < 2; mi++)
#pragma unroll
            for (int nb = 0; nb < 8; nb++) {
                MMA_BF16(acc[mi][nb], ah[mi][0], ah[mi][1], ah[mi][2], ah[mi][3],
                         bh[nb][0], bh[nb][1]);
                MMA_BF16(acc[mi][nb], ah[mi][0], ah[mi][1], ah[mi][2], ah[mi][3],
                         bl[nb][0], bl[nb][1]);
                MMA_BF16(acc[mi][nb], al[mi][0], al[mi][1], al[mi][2], al[mi][3],
                         bh[nb][0], bh[nb][1]);
            }
    }
    __syncthreads();   // done reading A/W tiles; reuse smem for C

    // Write accum frags to C[128][CSTRIDE]
    {
        float* C = (float*)smem;
        int t4r = l >> 2;
        int t4c = (l & 3) * 2;
#pragma unroll
        for (int mi = 0; mi < 2; mi++) {
            int row = wm * 32 + mi * 16 + t4r;
#pragma unroll
            for (int nb = 0; nb < 8; nb++) {
                int col = wn * 64 + nb * 8 + t4c;
                *(float2*)&C[row * CSTRIDE + col] =
                    make_float2(acc[mi][nb][0], acc[mi][nb][1]);
                *(float2*)&C[(row + 8) * CSTRIDE + col] =
                    make_float2(acc[mi][nb][2], acc[mi][nb][3]);
            }
        }
    }
    __syncthreads();

    // Scatter: 2 threads per edge, 16 red.v4 each
    {
        const float* C = (const float*)smem;
        int e  = tid >> 1;
        int hf = (tid & 1) << 6;
        float nm = norm[e0 + e];
        int d = load_idx(dstv, e0 + e, is64);
        float* po = out + (size_t)d * F + hf;
        const float* cr = C + e * CSTRIDE + hf;
#pragma unroll
        for (int q = 0; q < 16; q++) {
            float4 v = *(const float4*)(cr + q * 4);
            float x0 = v.x * nm, x1 = v.y * nm, x2 = v.z * nm, x3 = v.w * nm;
            asm volatile("red.global.add.v4.f32 [%0], {%1,%2,%3,%4};"
                         :: "l"(po + q * 4), "f"(x0), "f"(x1), "f"(x2), "f"(x3)
                         : "memory");
        }
    }
}

// ---------------------------------------------------------------------------
__global__ void relu_kernel(float* __restrict__ out) {
    int n4 = NN * F / 4;
    float4* p = (float4*)out;
    for (int i = blockIdx.x * blockDim.x + threadIdx.x; i < n4;
         i += gridDim.x * blockDim.x) {
        float4 v = p[i];
        v.x = fmaxf(v.x, 0.f);
        v.y = fmaxf(v.y, 0.f);
        v.z = fmaxf(v.z, 0.f);
        v.w = fmaxf(v.w, 0.f);
        p[i] = v;
    }
}

extern "C" void kernel_launch(void* const* d_in, const int* in_sizes, int n_in,
                              void* d_out, int out_size) {
    const float* feat   = (const float*)d_in[0];
    const float* weight = (const float*)d_in[1];
    const float* wcomp  = (const float*)d_in[2];
    const float* bias   = (const float*)d_in[3];
    const float* lw     = (const float*)d_in[4];
    const float* norm   = (const float*)d_in[5];
    const void*  src    = d_in[6];
    const void*  dst    = d_in[7];
    float* out = (float*)d_out;

    cudaFuncSetAttribute(edge_kernel,
                         cudaFuncAttributeMaxDynamicSharedMemorySize, EDGE_SMEM);
    cudaFuncSetAttribute(selfloop_kernel,
                         cudaFuncAttributeMaxDynamicSharedMemorySize, SL_SMEM);

    detect_kernel<<<1, 32>>>(src);
    basis_kernel<<<NRELS, 256>>>(weight, wcomp);
    selfloop_kernel<<<(NN + ET - 1) / ET, 512, SL_SMEM>>>(feat, lw, bias, out);
    edge_kernel<<<NE / EM, 256, EDGE_SMEM>>>(feat, norm, src, dst, out);
    relu_kernel<<<2048, 256>>>(out);
}

// round 10
// speedup vs baseline: 1.3902x; 1.1675x over previous
#include <cuda_runtime.h>
#include <cuda_bf16.h>
#include <stdint.h>

// Problem constants (fixed by the reference)
#define NRELS 64
#define EPR   16384
#define NE    (NRELS * EPR)         // 1,048,576 edges
#define NN    100000
#define F     128                   // in_feat == out_feat
#define NB    16

// ---------------- fp32 selfloop tile params ---------------------------------
#define ET    256
#define ES    260
#define SL_SMEM ((F * F + F * ES) * 4)

// ---------------- mma.sync edge kernel params -------------------------------
#define EM    128                   // edges per tile
#define TILE_BYTES 32768            // 128 rows x 128 bf16 (256 B/row, XOR swizzle)
#define OFF_WHI 0
#define OFF_WLO 32768
#define OFF_A0  65536               // half 0: Ahi @ +0, Alo @ +32768
#define OFF_A1  131072              // half 1
#define EDGE_SMEM 196608            // 192 KB

// Per-relation W^T hi/lo bf16, pre-laid-out as the exact 32KB smem tile image
__device__ __align__(16) unsigned char g_Whi[NRELS * TILE_BYTES]; // 2 MB
__device__ __align__(16) unsigned char g_Wlo[NRELS * TILE_BYTES]; // 2 MB
__device__ int g_idx64;

// ---------------------------------------------------------------------------
// Helpers
// ---------------------------------------------------------------------------
__device__ __forceinline__ uint32_t smem_u32(const void* p) {
    uint32_t a;
    asm("{ .reg .u64 t; cvta.to.shared.u64 t, %1; cvt.u32.u64 %0, t; }"
        : "=r"(a) : "l"(p));
    return a;
}

__device__ __forceinline__ uint32_t bf2_as_u32(__nv_bfloat162 v) {
    union { __nv_bfloat162 b; uint32_t u; } c;
    c.b = v;
    return c.u;
}

#define LDSM4(r0, r1, r2, r3, addr) \
    asm volatile("ldmatrix.sync.aligned.m8n8.x4.shared.b16 {%0,%1,%2,%3}, [%4];" \
                 : "=r"(r0), "=r"(r1), "=r"(r2), "=r"(r3) : "r"(addr))

#define MMA_BF16(d, a0, a1, a2, a3, b0, b1) \
    asm volatile("mma.sync.aligned.m16n8k16.row.col.f32.bf16.bf16.f32 " \
                 "{%0,%1,%2,%3}, {%4,%5,%6,%7}, {%8,%9}, {%0,%1,%2,%3};" \
                 : "+f"((d)[0]), "+f"((d)[1]), "+f"((d)[2]), "+f"((d)[3]) \
                 : "r"(a0), "r"(a1), "r"(a2), "r"(a3), "r"(b0), "r"(b1))

// bf16 tile address: row stride 256 B, 16B-chunk XOR swizzle (c ^= row&7)
__device__ __forceinline__ uint32_t btile_addr(int row, int col) {
    return (uint32_t)(row * 256 + ((((col >> 3) ^ (row & 7)) & 15) << 4)
                      + ((col & 7) << 1));
}

// ---------------------------------------------------------------------------
__global__ void detect_kernel(const void* __restrict__ src) {
    if (threadIdx.x == 0 && blockIdx.x == 0) {
        const unsigned long long* p = (const unsigned long long*)src;
        int all0 = 1;
#pragma unroll
        for (int i = 0; i < 8; i++) all0 &= ((p[i] >> 32) == 0ull);
        g_idx64 = all0;
    }
}
__device__ __forceinline__ int load_idx(const void* p, int i, int is64) {
    return is64 ? (int)((const long long*)p)[i] : ((const int*)p)[i];
}

// ---------------------------------------------------------------------------
// Basis composition -> per-relation W^T hi/lo bf16 tile images.
// o is the fast index so weight reads are coalesced (consecutive lanes ->
// consecutive o within one row k of weight[b]).
// ---------------------------------------------------------------------------
__global__ void basis_kernel(const float* __restrict__ weight,
                             const float* __restrict__ wcomp) {
    int r = blockIdx.x;
    __shared__ float s_wc[NB];
    if (threadIdx.x < NB) s_wc[threadIdx.x] = wcomp[r * NB + threadIdx.x];
    __syncthreads();
    for (int idx = threadIdx.x; idx < F * F; idx += blockDim.x) {
        int o = idx & 127;       // fast: coalesced weight reads
        int k = idx >> 7;
        float acc = 0.f;
#pragma unroll
        for (int b = 0; b < NB; b++)
            acc = fmaf(s_wc[b], weight[b * F * F + k * F + o], acc);
        uint32_t u = __float_as_uint(acc);
        float hf = __uint_as_float(u & 0xffff0000u);
        __nv_bfloat16 lo = __float2bfloat16(acc - hf);
        uint32_t a = btile_addr(o, k);   // tile row = o (N), tile col = k
        *(unsigned short*)(g_Whi + r * TILE_BYTES + a) = (unsigned short)(u >> 16);
        *(unsigned short*)(g_Wlo + r * TILE_BYTES + a) = __bfloat16_as_ushort(lo);
    }
}

// ---------------------------------------------------------------------------
// Self-loop + bias (fp32)
// ---------------------------------------------------------------------------
__global__ void __launch_bounds__(512, 1)
selfloop_kernel(const float* __restrict__ feat,
                const float* __restrict__ lw,
                const float* __restrict__ bias,
                float* __restrict__ out) {
    extern __shared__ float sm[];
    float* Ws = sm;
    float* A  = sm + F * F;
    int tid = threadIdx.x;
    int n0 = blockIdx.x * ET;
    {
        const float4* wg = (const float4*)lw;
        float4* ws4 = (float4*)Ws;
#pragma unroll
        for (int i = 0; i < 8; i++) ws4[tid + 512 * i] = wg[tid + 512 * i];
    }
    {
        int e  = tid >> 1;
        int kh = (tid & 1) << 6;
        int n  = n0 + e;
        int nn = (n < NN) ? n : 0;
        const float4* row = (const float4*)(feat + (size_t)nn * F + kh);
#pragma unroll
        for (int q = 0; q < 16; q++) {
            float4 v = row[q];
            int k = kh + q * 4;
            A[(k + 0) * ES + e] = v.x;
            A[(k + 1) * ES + e] = v.y;
            A[(k + 2) * ES + e] = v.z;
            A[(k + 3) * ES + e] = v.w;
        }
    }
    __syncthreads();

    int tx = tid & 15, ty = tid >> 4;
    float acc[8][8];
#pragma unroll
    for (int i = 0; i < 8; i++)
#pragma unroll
        for (int j = 0; j < 8; j++) acc[i][j] = 0.f;

    const float* Ap = A + ty * 8;
    const float* Bp = Ws + tx * 4;
#pragma unroll 8
    for (int k = 0; k < F; k++) {
        float4 a0 = *(const float4*)(Ap + k * ES);
        float4 a1 = *(const float4*)(Ap + k * ES + 4);
        float4 b0 = *(const float4*)(Bp + k * F);
        float4 b1 = *(const float4*)(Bp + k * F + 64);
        float av[8] = {a0.x, a0.y, a0.z, a0.w, a1.x, a1.y, a1.z, a1.w};
        float bv[8] = {b0.x, b0.y, b0.z, b0.w, b1.x, b1.y, b1.z, b1.w};
#pragma unroll
        for (int i = 0; i < 8; i++)
#pragma unroll
            for (int j = 0; j < 8; j++)
                acc[i][j] = fmaf(av[i], bv[j], acc[i][j]);
    }
    float4 bb0 = *(const float4*)(bias + tx * 4);
    float4 bb1 = *(const float4*)(bias + 64 + tx * 4);
#pragma unroll
    for (int i = 0; i < 8; i++) {
        int n = n0 + ty * 8 + i;
        if (n < NN) {
            float* po = out + (size_t)n * F + tx * 4;
            *(float4*)po = make_float4(acc[i][0] + bb0.x, acc[i][1] + bb0.y,
                                       acc[i][2] + bb0.z, acc[i][3] + bb0.w);
            *(float4*)(po + 64) = make_float4(acc[i][4] + bb1.x, acc[i][5] + bb1.y,
                                              acc[i][6] + bb1.z, acc[i][7] + bb1.w);
        }
    }
}

// ---------------------------------------------------------------------------
// Edge messages via mma.sync bf16 split.
// 512 threads = 2 halves; each half works a 128-edge tile; W shared in smem.
// Each CTA processes 4 tiles (2 concurrent x 2 iterations) of one relation.
// D = A_hi@Whi^T + A_hi@Wlo^T + A_lo@Whi^T, epilogue direct from registers
// via red.global.add.v2.f32.
// ---------------------------------------------------------------------------
__global__ void __launch_bounds__(512, 1)
edge_kernel(const float* __restrict__ feat,
            const float* __restrict__ norm,
            const void* __restrict__ srcv,
            const void* __restrict__ dstv,
            float* __restrict__ out) {
    extern __shared__ char smem[];
    uint32_t sb = smem_u32(smem);
    int tid  = threadIdx.x;
    int l    = tid & 31;
    int wid  = tid >> 5;
    int half = wid >> 3;             // which tile of the pair
    int hw   = wid & 7;              // warp within half
    int wm   = hw & 3;               // m-block: rows wm*32 .. +31
    int wn   = hw >> 2;              // n-block: cols wn*64 .. +63
    int rel  = blockIdx.x >> 5;      // 32 CTAs per relation
    int cidx = blockIdx.x & 31;
    int is64 = g_idx64;

    uint32_t offA = (half == 0) ? OFF_A0 : OFF_A1;

    // Stage W hi/lo once (pre-swizzled 32KB images, straight float4 copy)
    {
        const float4* wh = (const float4*)(g_Whi + rel * TILE_BYTES);
        const float4* wl = (const float4*)(g_Wlo + rel * TILE_BYTES);
        float4* sh = (float4*)(smem + OFF_WHI);
        float4* sl = (float4*)(smem + OFF_WLO);
#pragma unroll
        for (int i = 0; i < 4; i++) {
            sh[tid + 512 * i] = wh[tid + 512 * i];
            sl[tid + 512 * i] = wl[tid + 512 * i];
        }
    }

    // Fragment address precompute (within this half's A tile / shared W)
    uint32_t aOff[2], aSwz[2];
#pragma unroll
    for (int mi = 0; mi < 2; mi++) {
        int r = wm * 32 + mi * 16 + (l & 15);
        aOff[mi] = (uint32_t)(r * 256);
        aSwz[mi] = (uint32_t)(r & 7);
    }
    uint32_t aSel = (uint32_t)(l >> 4);
    uint32_t bOff[4], bSwz[4];
#pragma unroll
    for (int g = 0; g < 4; g++) {
        int r = wn * 64 + (2 * g + (l >> 4)) * 8 + (l & 7);
        bOff[g] = (uint32_t)(r * 256);
        bSwz[g] = (uint32_t)(r & 7);
    }
    uint32_t bSel = (uint32_t)((l >> 3) & 1);

    // gather mapping: 256 threads per half, 2 threads per edge
    int ht = tid & 255;
    int ge = ht >> 1;                // edge row 0..127
    int gk = (ht & 1) << 6;          // k half: 0 or 64

#pragma unroll 1
    for (int iter = 0; iter < 2; iter++) {
        int tileid = cidx * 4 + iter * 2 + half;
        int e0 = rel * EPR + tileid * EM;

        // ---- Gather source rows, split fp32 -> bf16 hi(trunc)/lo ----
        {
            int s = load_idx(srcv, e0 + ge, is64);
            const float4* row = (const float4*)(feat + (size_t)s * F + gk);
            uint32_t rbase = (uint32_t)(ge * 256);
            uint32_t rswz  = (uint32_t)(ge & 7);
#pragma unroll
            for (int q = 0; q < 8; q++) {
                float4 v0 = row[2 * q];
                float4 v1 = row[2 * q + 1];
                uint32_t u0 = __float_as_uint(v0.x), u1 = __float_as_uint(v0.y);
                uint32_t u2 = __float_as_uint(v0.z), u3 = __float_as_uint(v0.w);
                uint32_t u4 = __float_as_uint(v1.x), u5 = __float_as_uint(v1.y);
                uint32_t u6 = __float_as_uint(v1.z), u7 = __float_as_uint(v1.w);
                uint4 hv;
                hv.x = __byte_perm(u0, u1, 0x7632);
                hv.y = __byte_perm(u2, u3, 0x7632);
                hv.z = __byte_perm(u4, u5, 0x7632);
                hv.w = __byte_perm(u6, u7, 0x7632);
                float l0 = v0.x - __uint_as_float(u0 & 0xffff0000u);
                float l1 = v0.y - __uint_as_float(u1 & 0xffff0000u);
                float l2 = v0.z - __uint_as_float(u2 & 0xffff0000u);
                float l3 = v0.w - __uint_as_float(u3 & 0xffff0000u);
                float l4 = v1.x - __uint_as_float(u4 & 0xffff0000u);
                float l5 = v1.y - __uint_as_float(u5 & 0xffff0000u);
                float l6 = v1.z - __uint_as_float(u6 & 0xffff0000u);
                float l7 = v1.w - __uint_as_float(u7 & 0xffff0000u);
                uint4 lv;
                lv.x = bf2_as_u32(__floats2bfloat162_rn(l0, l1));
                lv.y = bf2_as_u32(__floats2bfloat162_rn(l2, l3));
                lv.z = bf2_as_u32(__floats2bfloat162_rn(l4, l5));
                lv.w = bf2_as_u32(__floats2bfloat162_rn(l6, l7));
                uint32_t chunk = (uint32_t)((gk >> 3) + q);
                uint32_t off = rbase + ((chunk ^ rswz) << 4);
                *(uint4*)(smem + offA + off) = hv;
                *(uint4*)(smem + offA + 32768 + off) = lv;
            }
        }
        __syncthreads();

        // ---- MMA ----
        float acc[2][8][4];
#pragma unroll
        for (int mi = 0; mi < 2; mi++)
#pragma unroll
            for (int nb = 0; nb < 8; nb++)
#pragma unroll
                for (int j = 0; j < 4; j++) acc[mi][nb][j] = 0.f;

#pragma unroll
        for (int ks = 0; ks < 8; ks++) {
            uint32_t cA = 2 * ks + aSel;
            uint32_t cB = 2 * ks + bSel;
            uint32_t ah[2][4], al[2][4];
#pragma unroll
            for (int mi = 0; mi < 2; mi++) {
                uint32_t ad = sb + offA + aOff[mi] + (((cA ^ aSwz[mi]) & 15) << 4);
                LDSM4(ah[mi][0], ah[mi][1], ah[mi][2], ah[mi][3], ad);
                LDSM4(al[mi][0], al[mi][1], al[mi][2], al[mi][3], ad + 32768);
            }
#pragma unroll
            for (int g = 0; g < 4; g++) {
                uint32_t bd = sb + bOff[g] + (((cB ^ bSwz[g]) & 15) << 4);
                uint32_t bh0, bh1, bh2, bh3, bl0, bl1, bl2, bl3;
                LDSM4(bh0, bh1, bh2, bh3, bd + OFF_WHI);
                LDSM4(bl0, bl1, bl2, bl3, bd + OFF_WLO);
#pragma unroll
                for (int mi = 0; mi < 2; mi++) {
                    MMA_BF16(acc[mi][2 * g], ah[mi][0], ah[mi][1], ah[mi][2],
                             ah[mi][3], bh0, bh1);
                    MMA_BF16(acc[mi][2 * g + 1], ah[mi][0], ah[mi][1], ah[mi][2],
                             ah[mi][3], bh2, bh3);
                    MMA_BF16(acc[mi][2 * g], ah[mi][0], ah[mi][1], ah[mi][2],
                             ah[mi][3], bl0, bl1);
                    MMA_BF16(acc[mi][2 * g + 1], ah[mi][0], ah[mi][1], ah[mi][2],
                             ah[mi][3], bl2, bl3);
                    MMA_BF16(acc[mi][2 * g], al[mi][0], al[mi][1], al[mi][2],
                             al[mi][3], bh0, bh1);
                    MMA_BF16(acc[mi][2 * g + 1], al[mi][0], al[mi][1], al[mi][2],
                             al[mi][3], bh2, bh3);
                }
            }
        }
        __syncthreads();   // A buffer free for next iteration

        // ---- Epilogue: scale by norm, scatter via red.v2 ----
        {
            int t4r = l >> 2;
            int t4c = (l & 3) * 2;
#pragma unroll
            for (int mi = 0; mi < 2; mi++) {
#pragma unroll
                for (int rp = 0; rp < 2; rp++) {
                    int row = wm * 32 + mi * 16 + t4r + rp * 8;
                    int e = e0 + row;
                    float nm = norm[e];
                    int d = load_idx(dstv, e, is64);
                    float* po = out + (size_t)d * F + wn * 64 + t4c;
#pragma unroll
                    for (int nb = 0; nb < 8; nb++) {
                        float x0 = acc[mi][nb][2 * rp] * nm;
                        float x1 = acc[mi][nb][2 * rp + 1] * nm;
                        asm volatile("red.global.add.v2.f32 [%0], {%1,%2};"
                                     :: "l"(po + nb * 8), "f"(x0), "f"(x1)
                                     : "memory");
                    }
                }
            }
        }
    }
}

// ---------------------------------------------------------------------------
__global__ void relu_kernel(float* __restrict__ out) {
    int n4 = NN * F / 4;
    float4* p = (float4*)out;
    for (int i = blockIdx.x * blockDim.x + threadIdx.x; i < n4;
         i += gridDim.x * blockDim.x) {
        float4 v = p[i];
        v.x = fmaxf(v.x, 0.f);
        v.y = fmaxf(v.y, 0.f);
        v.z = fmaxf(v.z, 0.f);
        v.w = fmaxf(v.w, 0.f);
        p[i] = v;
    }
}

extern "C" void kernel_launch(void* const* d_in, const int* in_sizes, int n_in,
                              void* d_out, int out_size) {
    const float* feat   = (const float*)d_in[0];
    const float* weight = (const float*)d_in[1];
    const float* wcomp  = (const float*)d_in[2];
    const float* bias   = (const float*)d_in[3];
    const float* lw     = (const float*)d_in[4];
    const float* norm   = (const float*)d_in[5];
    const void*  src    = d_in[6];
    const void*  dst    = d_in[7];
    float* out = (float*)d_out;

    cudaFuncSetAttribute(edge_kernel,
                         cudaFuncAttributeMaxDynamicSharedMemorySize, EDGE_SMEM);
    cudaFuncSetAttribute(selfloop_kernel,
                         cudaFuncAttributeMaxDynamicSharedMemorySize, SL_SMEM);

    detect_kernel<<<1, 32>>>(src);
    basis_kernel<<<NRELS, 256>>>(weight, wcomp);
    selfloop_kernel<<<(NN + ET - 1) / ET, 512, SL_SMEM>>>(feat, lw, bias, out);
    edge_kernel<<<2048, 512, EDGE_SMEM>>>(feat, norm, src, dst, out);
    relu_kernel<<<2048, 256>>>(out);
}